// round 11
// baseline (speedup 1.0000x reference)
#include <cuda_runtime.h>
#include <cuda_bf16.h>
#include <cstdint>

// Problem constants
#define N_   32
#define C_   64
#define T_   300
#define V_   25
#define O_   128
#define TO_  150
#define TV_  7500
#define TOV_ 3750
#define KT_  9

// Phase-split transposed agg layout: [n][v][row][c], row<224: even phase
// (t_in = 2*(row-2)), row>=224: odd phase (t_in = 2*(row-224-2)+1).
#define ROWS_ 448
// x_sub layout rows (t_out 0..149 valid, 150..191 zero)
#define XROWS_ 192

__device__ float g_xtcn[N_ * O_ * TO_ * V_];         // 61.4 MB fp32
__device__ float g_beff[O_ * TO_];
__device__ __align__(16) unsigned short g_aggBH[(size_t)N_ * V_ * ROWS_ * 64];
__device__ __align__(16) unsigned short g_aggBL[(size_t)N_ * V_ * ROWS_ * 64];
__device__ __align__(16) unsigned short g_xsubBH[(size_t)N_ * V_ * XROWS_ * 64];
__device__ __align__(16) unsigned short g_xsubBL[(size_t)N_ * V_ * XROWS_ * 64];
__device__ __align__(16) unsigned short g_WtapH[9 * 128 * 64];
__device__ __align__(16) unsigned short g_WtapL[9 * 128 * 64];
__device__ __align__(16) unsigned short g_WresH[128 * 64];
__device__ __align__(16) unsigned short g_WresL[128 * 64];
__device__ double g_sum[O_];
__device__ double g_sum2[O_];
__device__ float g_scale[O_];
__device__ float g_shift[O_];

// ---------------- PTX helpers ------------------------------------------------
__device__ __forceinline__ uint32_t smem_u32(const void* p) {
    uint32_t a;
    asm("{ .reg .u64 t; cvta.to.shared.u64 t, %1; cvt.u32.u64 %0, t; }" : "=r"(a) : "l"(p));
    return a;
}
__device__ __forceinline__ void ldsm_x4(uint32_t* r, uint32_t addr) {
    asm volatile("ldmatrix.sync.aligned.m8n8.x4.shared.b16 {%0,%1,%2,%3}, [%4];"
                 : "=r"(r[0]), "=r"(r[1]), "=r"(r[2]), "=r"(r[3]) : "r"(addr));
}
__device__ __forceinline__ void mma_bf16(float* d, const uint32_t* a, const uint32_t* b) {
    asm volatile(
        "mma.sync.aligned.m16n8k16.row.col.f32.bf16.bf16.f32 "
        "{%0,%1,%2,%3}, {%4,%5,%6,%7}, {%8,%9}, {%0,%1,%2,%3};"
        : "+f"(d[0]), "+f"(d[1]), "+f"(d[2]), "+f"(d[3])
        : "r"(a[0]), "r"(a[1]), "r"(a[2]), "r"(a[3]), "r"(b[0]), "r"(b[1]));
}
#define SWZ128(x) ((x) ^ (((x) >> 3) & 0x70))

// ---------------------------------------------------------------------------
// L1: k_wprep — fused gcn*tcn weight -> swizzled bf16 hi/lo per-tap images.
// ---------------------------------------------------------------------------
__global__ void __launch_bounds__(128) k_wprep(const float* __restrict__ tcn_w,
                                               const float* __restrict__ gcn_w) {
    __shared__ float gc[O_];
    int ck = blockIdx.x;
    int c = ck / KT_, k = ck % KT_;
    int o = threadIdx.x;
    gc[o] = gcn_w[o * C_ + c];
    __syncthreads();
    const float* wrow = tcn_w + (size_t)o * O_ * KT_ + k;
    float s = 0.f;
    #pragma unroll 8
    for (int o2 = 0; o2 < O_; o2++) s += wrow[o2 * KT_] * gc[o2];
    __nv_bfloat16 h = __float2bfloat16(s);
    __nv_bfloat16 l = __float2bfloat16(s - __bfloat162float(h));
    uint32_t boff = SWZ128((uint32_t)(o * 128 + c * 2));
    g_WtapH[k * 8192 + (boff >> 1)] = *reinterpret_cast<unsigned short*>(&h);
    g_WtapL[k * 8192 + (boff >> 1)] = *reinterpret_cast<unsigned short*>(&l);
}

// ---------------------------------------------------------------------------
// L2: k_beff — bias_eff + zero stats accumulators + res_w swizzled images
// ---------------------------------------------------------------------------
__global__ void __launch_bounds__(128) k_beff(const float* __restrict__ tcn_w,
                                              const float* __restrict__ gcn_b,
                                              const float* __restrict__ tcn_b,
                                              const float* __restrict__ res_w) {
    __shared__ float red[128];
    __shared__ float Bk[KT_];
    int o = blockIdx.x, o2 = threadIdx.x;
    if (o2 == 0) { g_sum[o] = 0.0; g_sum2[o] = 0.0; }
    // res_w image rows for this o-block: each block writes row o (64 entries)
    {
        // thread o2 handles column pairs: 64 cols, 128 threads -> half active
        if (o2 < 64) {
            float w = res_w[o * C_ + o2];
            __nv_bfloat16 h = __float2bfloat16(w);
            __nv_bfloat16 l = __float2bfloat16(w - __bfloat162float(h));
            uint32_t boff = SWZ128((uint32_t)(o * 128 + o2 * 2));
            g_WresH[boff >> 1] = *reinterpret_cast<unsigned short*>(&h);
            g_WresL[boff >> 1] = *reinterpret_cast<unsigned short*>(&l);
        }
    }
    float gb = gcn_b[o2];
    const float* wrow = tcn_w + ((size_t)o * O_ + o2) * KT_;
    #pragma unroll
    for (int k = 0; k < KT_; k++) {
        red[o2] = wrow[k] * gb;
        __syncthreads();
        for (int st = 64; st > 0; st >>= 1) {
            if (o2 < st) red[o2] += red[o2 + st];
            __syncthreads();
        }
        if (o2 == 0) Bk[k] = red[0];
        __syncthreads();
    }
    float tb = tcn_b[o];
    for (int t = threadIdx.x; t < TO_; t += 128) {
        float s = tb;
        #pragma unroll
        for (int k = 0; k < KT_; k++) {
            int tp = 2 * t + k - 4;
            if (tp >= 0 && tp < T_) s += Bk[k];
        }
        g_beff[o * TO_ + t] = s;
    }
}

// ---------------------------------------------------------------------------
// L3: k_aggp — agg in phase-split transposed bf16 hi/lo layout; also emits
// raw x_sub (even-phase x) in [n][v][t_out][c] bf16 hi/lo layout.
// ---------------------------------------------------------------------------
__global__ void __launch_bounds__(256) k_aggp(const float* __restrict__ x,
                                              const float* __restrict__ A_parts,
                                              const float* __restrict__ ei) {
    __shared__ float sx[1600];
    __shared__ float As[625];
    __shared__ __align__(16) unsigned short souts[2][1600];
    __shared__ __align__(16) unsigned short souts2[2][1600];
    int row = blockIdx.x, n = blockIdx.y, tid = threadIdx.x;
    int phase = (row >= 224) ? 1 : 0;
    int e = phase ? (row - 224) : row;
    int t_in = 2 * (e - 2) + phase;
    bool valid = (t_in >= 0) && (t_in < T_);
    int tout = row - 2;           // only meaningful for phase==0

    if (valid) {
        float e0 = ei[0], e1 = ei[1], e2 = ei[2];
        for (int i = tid; i < 625; i += 256)
            As[i] = A_parts[i] * e0 + A_parts[625 + i] * e1 + A_parts[1250 + i] * e2;
        const float* xb = x + ((size_t)n * C_) * TV_ + t_in * V_;
        for (int i = tid; i < 1600; i += 256) {
            int c = i / 25, w = i - c * 25;
            sx[i] = xb[c * TV_ + w];
        }
        __syncthreads();
        for (int i = tid; i < 1600; i += 256) {
            int v = i >> 6, c = i & 63;
            float s = 0.f;
            #pragma unroll
            for (int w = 0; w < 25; w++) s += sx[c * 25 + w] * As[w * 25 + v];
            __nv_bfloat16 h = __float2bfloat16(s);
            __nv_bfloat16 l = __float2bfloat16(s - __bfloat162float(h));
            souts[0][v * 64 + c] = *reinterpret_cast<unsigned short*>(&h);
            souts[1][v * 64 + c] = *reinterpret_cast<unsigned short*>(&l);
            float xv = sx[c * 25 + v];
            __nv_bfloat16 xh = __float2bfloat16(xv);
            __nv_bfloat16 xl = __float2bfloat16(xv - __bfloat162float(xh));
            souts2[0][v * 64 + c] = *reinterpret_cast<unsigned short*>(&xh);
            souts2[1][v * 64 + c] = *reinterpret_cast<unsigned short*>(&xl);
        }
        __syncthreads();
        int r7 = row & 7;
        for (int j = tid; j < 400; j += 256) {
            int v = j >> 4, qq = j & 15, arr = qq >> 3, q = qq & 7;
            uint4 val = *(const uint4*)&souts[arr][v * 64 + ((q ^ r7) << 3)];
            unsigned short* base = arr ? g_aggBL : g_aggBH;
            *((uint4*)(base + (((size_t)(n * 25 + v) * ROWS_ + row) << 6)) + q) = val;
        }
        if (phase == 0 && tout >= 0 && tout < XROWS_) {
            int r7x = tout & 7;
            for (int j = tid; j < 400; j += 256) {
                int v = j >> 4, qq = j & 15, arr = qq >> 3, q = qq & 7;
                uint4 val = *(const uint4*)&souts2[arr][v * 64 + ((q ^ r7x) << 3)];
                unsigned short* base = arr ? g_xsubBL : g_xsubBH;
                *((uint4*)(base + (((size_t)(n * 25 + v) * XROWS_ + tout) << 6)) + q) = val;
            }
        }
    } else {
        for (int j = tid; j < 400; j += 256) {
            int v = j >> 4, qq = j & 15, arr = qq >> 3, q = qq & 7;
            unsigned short* base = arr ? g_aggBL : g_aggBH;
            *((uint4*)(base + (((size_t)(n * 25 + v) * ROWS_ + row) << 6)) + q) =
                make_uint4(0, 0, 0, 0);
        }
        if (phase == 0 && tout >= 0 && tout < XROWS_) {
            for (int j = tid; j < 400; j += 256) {
                int v = j >> 4, qq = j & 15, arr = qq >> 3, q = qq & 7;
                unsigned short* base = arr ? g_xsubBL : g_xsubBH;
                *((uint4*)(base + (((size_t)(n * 25 + v) * XROWS_ + tout) << 6)) + q) =
                    make_uint4(0, 0, 0, 0);
            }
        }
    }
}

// ---------------------------------------------------------------------------
// L4 (profiled slot): k_tcn_mma — tap-shift HMMA, 2 v per CTA (N=128),
// fused BN-stats accumulation, x4 B-loads.
// ---------------------------------------------------------------------------
#define R_SEC  72
#define SEC_B  (R_SEC * 128)          // 9216
#define BH_OFF 0
#define BL_OFF (4 * SEC_B)            // 36864
#define AH_OFF (8 * SEC_B)            // 73728
#define AL_OFF (AH_OFF + 16384)       // 90112
#define SMEM_TOT (AL_OFF + 16384)     // 106496

__global__ void __launch_bounds__(256, 2) k_tcn_mma() {
    extern __shared__ __align__(16) unsigned char smem[];
    int tid = threadIdx.x, lane = tid & 31, wid = tid >> 5;
    int wm = wid >> 2, wn = wid & 3;
    int t0 = blockIdx.x * 64;
    int v0 = blockIdx.y * 2;
    int n = blockIdx.z;
    uint32_t sbase = smem_u32(smem);

    // ---- B copy: 4 sections (vsec,phase) x 72 rows; pad rows / invalid v -> 0
    for (int j = tid; j < 4608; j += 256) {
        int arr = (j >= 2304) ? 1 : 0;
        int r = arr ? (j - 2304) : j;
        int sec = r / 576;
        int rq = r - sec * 576;
        int row = rq >> 3, q = rq & 7;
        int vsec = sec >> 1, phase = sec & 1;
        int vv = v0 + vsec;
        uint4 val = make_uint4(0, 0, 0, 0);
        if (row < 68 && vv < V_) {
            int grow = (phase ? 224 : 0) + t0 + row;
            const unsigned short* g = (arr ? g_aggBL : g_aggBH) +
                (((size_t)(n * V_ + vv) * ROWS_ + grow) << 6);
            val = *((const uint4*)g + q);
        }
        *((uint4*)(smem + (arr ? BL_OFF : BH_OFF) + sec * SEC_B + row * 128) + q) = val;
    }

    // fragment addressing
    int la_row = ((lane >> 3) & 1) * 8 + (lane & 7);
    uint32_t xorA = (uint32_t)((lane & 7) << 4);
    uint32_t la_col = ((lane >> 4) & 1) * 16;
    uint32_t aRow = (uint32_t)(wm * 64 + la_row) * 128;
    int vsec_w = wn >> 1, trow = (wn & 1) * 32;
    uint32_t lb_col = (uint32_t)(((lane >> 3) & 1) * 16);
    uint32_t lrow8 = (uint32_t)(((lane >> 4) & 1) * 8 + (lane & 7));

    float acc[4][4][4] = {};

    for (int k = 0; k < 9; k++) {
        __syncthreads();
        for (int j = tid; j < 2048; j += 256) {
            int p = j >> 10, idx = j & 1023;
            *((uint4*)(smem + (p ? AL_OFF : AH_OFF)) + idx) =
                *((const uint4*)((p ? g_WtapL : g_WtapH) + k * 8192) + idx);
        }
        __syncthreads();

        int phase = k & 1, jt = k >> 1;
        uint32_t secoff = (uint32_t)(vsec_w * 2 + phase) * SEC_B;
        uint32_t xorB = (uint32_t)(((jt + (lane & 7)) & 7) << 4);
        uint32_t rb4 = (uint32_t)(jt + trow) + lrow8;   // rows for x4 (2 nt tiles)

        #pragma unroll
        for (int ks = 0; ks < 4; ks++) {
            uint32_t cb = ((uint32_t)(ks * 32) + lb_col) ^ xorB;
            uint32_t bh[4][2], bl[4][2];
            {
                uint32_t a0 = sbase + BH_OFF + secoff + rb4 * 128 + cb;
                ldsm_x4(&bh[0][0], a0);
                ldsm_x4(&bh[2][0], a0 + 16 * 128);
                uint32_t a1 = sbase + BL_OFF + secoff + rb4 * 128 + cb;
                ldsm_x4(&bl[0][0], a1);
                ldsm_x4(&bl[2][0], a1 + 16 * 128);
            }
            uint32_t ca = ((uint32_t)(ks * 32) + la_col) ^ xorA;
            #pragma unroll
            for (int mt = 0; mt < 4; mt++) {
                uint32_t ah[4], al[4];
                ldsm_x4(ah, sbase + AH_OFF + aRow + mt * 2048 + ca);
                ldsm_x4(al, sbase + AL_OFF + aRow + mt * 2048 + ca);
                #pragma unroll
                for (int nt = 0; nt < 4; nt++) {
                    mma_bf16(acc[mt][nt], ah, bh[nt]);
                    mma_bf16(acc[mt][nt], ah, bl[nt]);
                    mma_bf16(acc[mt][nt], al, bh[nt]);
                }
            }
        }
    }

    // ---- epilogue + fused stats
    __syncthreads();
    float* ssum = (float*)smem;
    float* ssum2 = ssum + 128;
    if (tid < 128) { ssum[tid] = 0.f; ssum2[tid] = 0.f; }
    __syncthreads();

    float* Out = g_xtcn + (size_t)n * O_ * TOV_;
    int qr = lane >> 2, qc = (lane & 3) * 2;
    int vv = v0 + vsec_w;
    #pragma unroll
    for (int mt = 0; mt < 4; mt++) {
        #pragma unroll
        for (int hh = 0; hh < 2; hh++) {
            int o = wm * 64 + mt * 16 + qr + hh * 8;
            const float* be = g_beff + o * TO_;
            float* orow = Out + (size_t)o * TOV_;
            float s1 = 0.f, s2 = 0.f;
            #pragma unroll
            for (int nt = 0; nt < 4; nt++) {
                int t = t0 + trow + nt * 8 + qc;
                if (vv < V_) {
                    if (t < TO_) {
                        float y = acc[mt][nt][hh * 2 + 0] + be[t];
                        orow[t * V_ + vv] = y;
                        s1 += y; s2 += y * y;
                    }
                    if (t + 1 < TO_) {
                        float y = acc[mt][nt][hh * 2 + 1] + be[t + 1];
                        orow[(t + 1) * V_ + vv] = y;
                        s1 += y; s2 += y * y;
                    }
                }
            }
            s1 += __shfl_xor_sync(0xFFFFFFFFu, s1, 1);
            s1 += __shfl_xor_sync(0xFFFFFFFFu, s1, 2);
            s2 += __shfl_xor_sync(0xFFFFFFFFu, s2, 1);
            s2 += __shfl_xor_sync(0xFFFFFFFFu, s2, 2);
            if ((lane & 3) == 0) {
                atomicAdd(&ssum[o], s1);
                atomicAdd(&ssum2[o], s2);
            }
        }
    }
    __syncthreads();
    if (tid < 128) {
        atomicAdd(&g_sum[tid], (double)ssum[tid]);
        atomicAdd(&g_sum2[tid], (double)ssum2[tid]);
    }
}

// ---------------------------------------------------------------------------
// L5: k_statsfin — finalize BN scale/shift (res_b folded into shift)
// ---------------------------------------------------------------------------
__global__ void k_statsfin(const float* __restrict__ gamma,
                           const float* __restrict__ beta,
                           const float* __restrict__ res_b) {
    int o = threadIdx.x;
    double cnt = (double)N_ * (double)TOV_;
    double mean = g_sum[o] / cnt;
    double var = g_sum2[o] / cnt - mean * mean;
    float rstd = (float)(1.0 / sqrt(var + 1e-5));
    float sc = gamma[o] * rstd;
    g_scale[o] = sc;
    g_shift[o] = beta[o] - (float)mean * sc + res_b[o];
}

// ---------------------------------------------------------------------------
// L6: k_final_mma — residual HMMA (K=64, 3-term) + BN affine + add + ReLU.
// CTA = (t-block 64, v-pair, n); N=128 (2 v sections x 64 t).
// smem: Bh 2x8KB | Bl 2x8KB | Ah 16KB | Al 16KB = 64KB
// ---------------------------------------------------------------------------
#define FSEC_B 8192
#define FBH 0
#define FBL 16384
#define FAH 32768
#define FAL 49152
#define SMEM_FIN 65536

__global__ void __launch_bounds__(256, 2) k_final_mma(float* __restrict__ out) {
    extern __shared__ __align__(16) unsigned char smem[];
    int tid = threadIdx.x, lane = tid & 31, wid = tid >> 5;
    int wm = wid >> 2, wn = wid & 3;
    int t0 = blockIdx.x * 64;
    int v0 = blockIdx.y * 2;
    int n = blockIdx.z;
    uint32_t sbase = smem_u32(smem);

    // B copy: 2 arrays x 2 sections x 64 rows x 8 q
    for (int j = tid; j < 2048; j += 256) {
        int arr = (j >= 1024) ? 1 : 0;
        int r = j & 1023;
        int sec = r >> 9;
        int rq = r & 511;
        int row = rq >> 3, q = rq & 7;
        int vv = v0 + sec;
        uint4 val = make_uint4(0, 0, 0, 0);
        if (vv < V_) {
            const unsigned short* g = (arr ? g_xsubBL : g_xsubBH) +
                (((size_t)(n * V_ + vv) * XROWS_ + t0 + row) << 6);
            val = *((const uint4*)g + q);
        }
        *((uint4*)(smem + (arr ? FBL : FBH) + sec * FSEC_B + row * 128) + q) = val;
    }
    // A copy (res_w images)
    for (int j = tid; j < 2048; j += 256) {
        int p = j >> 10, idx = j & 1023;
        *((uint4*)(smem + (p ? FAL : FAH)) + idx) =
            *((const uint4*)(p ? g_WresL : g_WresH) + idx);
    }
    __syncthreads();

    int la_row = ((lane >> 3) & 1) * 8 + (lane & 7);
    uint32_t xorA = (uint32_t)((lane & 7) << 4);
    uint32_t la_col = ((lane >> 4) & 1) * 16;
    uint32_t aRow = (uint32_t)(wm * 64 + la_row) * 128;
    int vsec_w = wn >> 1, trow = (wn & 1) * 32;
    uint32_t lb_col = (uint32_t)(((lane >> 3) & 1) * 16);
    uint32_t lrow8 = (uint32_t)(((lane >> 4) & 1) * 8 + (lane & 7));
    uint32_t xorB = (uint32_t)((lane & 7) << 4);
    uint32_t secoff = (uint32_t)vsec_w * FSEC_B;
    uint32_t rb4 = (uint32_t)trow + lrow8;

    float acc[4][4][4] = {};

    #pragma unroll
    for (int ks = 0; ks < 4; ks++) {
        uint32_t cb = ((uint32_t)(ks * 32) + lb_col) ^ xorB;
        uint32_t bh[4][2], bl[4][2];
        {
            uint32_t a0 = sbase + FBH + secoff + rb4 * 128 + cb;
            ldsm_x4(&bh[0][0], a0);
            ldsm_x4(&bh[2][0], a0 + 16 * 128);
            uint32_t a1 = sbase + FBL + secoff + rb4 * 128 + cb;
            ldsm_x4(&bl[0][0], a1);
            ldsm_x4(&bl[2][0], a1 + 16 * 128);
        }
        uint32_t ca = ((uint32_t)(ks * 32) + la_col) ^ xorA;
        #pragma unroll
        for (int mt = 0; mt < 4; mt++) {
            uint32_t ah[4], al[4];
            ldsm_x4(ah, sbase + FAH + aRow + mt * 2048 + ca);
            ldsm_x4(al, sbase + FAL + aRow + mt * 2048 + ca);
            #pragma unroll
            for (int nt = 0; nt < 4; nt++) {
                mma_bf16(acc[mt][nt], ah, bh[nt]);
                mma_bf16(acc[mt][nt], ah, bl[nt]);
                mma_bf16(acc[mt][nt], al, bh[nt]);
            }
        }
    }

    // epilogue: out = relu(xtcn*scale + shift(+res_b) + res)
    const float* Tcn = g_xtcn + (size_t)n * O_ * TOV_;
    float* Out = out + (size_t)n * O_ * TOV_;
    int qr = lane >> 2, qc = (lane & 3) * 2;
    int vv = v0 + vsec_w;
    #pragma unroll
    for (int mt = 0; mt < 4; mt++) {
        #pragma unroll
        for (int hh = 0; hh < 2; hh++) {
            int o = wm * 64 + mt * 16 + qr + hh * 8;
            float sc = g_scale[o];
            float sh = g_shift[o];
            const float* trow_p = Tcn + (size_t)o * TOV_;
            float* orow = Out + (size_t)o * TOV_;
            #pragma unroll
            for (int nt = 0; nt < 4; nt++) {
                int t = t0 + trow + nt * 8 + qc;
                if (vv < V_) {
                    if (t < TO_) {
                        float y = trow_p[t * V_ + vv] * sc + sh + acc[mt][nt][hh * 2 + 0];
                        orow[t * V_ + vv] = fmaxf(y, 0.f);
                    }
                    if (t + 1 < TO_) {
                        float y = trow_p[(t + 1) * V_ + vv] * sc + sh + acc[mt][nt][hh * 2 + 1];
                        orow[(t + 1) * V_ + vv] = fmaxf(y, 0.f);
                    }
                }
            }
        }
    }
}

// ---------------------------------------------------------------------------
extern "C" void kernel_launch(void* const* d_in, const int* in_sizes, int n_in,
                              void* d_out, int out_size) {
    const float* x       = (const float*)d_in[0];
    const float* A_parts = (const float*)d_in[1];
    const float* ei      = (const float*)d_in[2];
    const float* gcn_w   = (const float*)d_in[3];
    const float* gcn_b   = (const float*)d_in[4];
    const float* tcn_w   = (const float*)d_in[5];
    const float* tcn_b   = (const float*)d_in[6];
    const float* bn_g    = (const float*)d_in[7];
    const float* bn_b    = (const float*)d_in[8];
    const float* res_w   = (const float*)d_in[9];
    const float* res_b   = (const float*)d_in[10];
    float* out = (float*)d_out;

    cudaFuncSetAttribute(k_tcn_mma, cudaFuncAttributeMaxDynamicSharedMemorySize,
                         SMEM_TOT);
    cudaFuncSetAttribute(k_final_mma, cudaFuncAttributeMaxDynamicSharedMemorySize,
                         SMEM_FIN);

    k_wprep<<<576, 128>>>(tcn_w, gcn_w);                 // 1
    k_beff<<<O_, 128>>>(tcn_w, gcn_b, tcn_b, res_w);     // 2
    dim3 gagg(ROWS_, N_);
    k_aggp<<<gagg, 256>>>(x, A_parts, ei);               // 3
    dim3 gtcn(3, 13, N_);
    k_tcn_mma<<<gtcn, 256, SMEM_TOT>>>();                // 4  <- profiled
    k_statsfin<<<1, 128>>>(bn_g, bn_b, res_b);           // 5
    dim3 gfin(3, 13, N_);
    k_final_mma<<<gfin, 256, SMEM_FIN>>>(out);           // 6
}

// round 12
// speedup vs baseline: 1.4517x; 1.4517x over previous
#include <cuda_runtime.h>
#include <cuda_fp16.h>
#include <cstdint>

// Problem constants
#define N_   32
#define C_   64
#define T_   300
#define V_   25
#define O_   128
#define TO_  150
#define TV_  7500
#define TOV_ 3750
#define KT_  9

// Phase-split transposed agg layout: [n][v][row][c], row<224: even phase
// (t_in = 2*(row-2)), row>=224: odd phase (t_in = 2*(row-224-2)+1).
#define ROWS_ 448

__device__ float g_xtcn[N_ * O_ * TO_ * V_];         // 61.4 MB fp32
__device__ float g_beff[O_ * TO_];
__device__ __align__(16) unsigned short g_aggB[(size_t)N_ * V_ * ROWS_ * 64];  // fp16
__device__ __align__(16) unsigned short g_WtapH[9 * 128 * 64];  // fp16 hi
__device__ __align__(16) unsigned short g_WtapL[9 * 128 * 64];  // fp16 lo
__device__ double g_sum[O_];
__device__ double g_sum2[O_];
__device__ float g_scale[O_];
__device__ float g_shift[O_];

// ---------------- PTX helpers ------------------------------------------------
__device__ __forceinline__ uint32_t smem_u32(const void* p) {
    uint32_t a;
    asm("{ .reg .u64 t; cvta.to.shared.u64 t, %1; cvt.u32.u64 %0, t; }" : "=r"(a) : "l"(p));
    return a;
}
__device__ __forceinline__ void ldsm_x4(uint32_t* r, uint32_t addr) {
    asm volatile("ldmatrix.sync.aligned.m8n8.x4.shared.b16 {%0,%1,%2,%3}, [%4];"
                 : "=r"(r[0]), "=r"(r[1]), "=r"(r[2]), "=r"(r[3]) : "r"(addr));
}
__device__ __forceinline__ void mma_f16(float* d, const uint32_t* a, const uint32_t* b) {
    asm volatile(
        "mma.sync.aligned.m16n8k16.row.col.f32.f16.f16.f32 "
        "{%0,%1,%2,%3}, {%4,%5,%6,%7}, {%8,%9}, {%0,%1,%2,%3};"
        : "+f"(d[0]), "+f"(d[1]), "+f"(d[2]), "+f"(d[3])
        : "r"(a[0]), "r"(a[1]), "r"(a[2]), "r"(a[3]), "r"(b[0]), "r"(b[1]));
}
__device__ __forceinline__ void cp_async16(uint32_t dst, const void* src) {
    asm volatile("cp.async.cg.shared.global [%0], [%1], 16;" :: "r"(dst), "l"(src));
}
#define CP_COMMIT() asm volatile("cp.async.commit_group;" ::: "memory")
#define CP_WAIT0()  asm volatile("cp.async.wait_group 0;" ::: "memory")
#define SWZ128(x) ((x) ^ (((x) >> 3) & 0x70))

// ---------------------------------------------------------------------------
// L1: k_wprep — fused gcn*tcn weight -> swizzled fp16 hi/lo per-tap images.
// ---------------------------------------------------------------------------
__global__ void __launch_bounds__(128) k_wprep(const float* __restrict__ tcn_w,
                                               const float* __restrict__ gcn_w) {
    __shared__ float gc[O_];
    int ck = blockIdx.x;
    int c = ck / KT_, k = ck % KT_;
    int o = threadIdx.x;
    gc[o] = gcn_w[o * C_ + c];
    __syncthreads();
    const float* wrow = tcn_w + (size_t)o * O_ * KT_ + k;
    float s = 0.f;
    #pragma unroll 8
    for (int o2 = 0; o2 < O_; o2++) s += wrow[o2 * KT_] * gc[o2];
    __half h = __float2half_rn(s);
    __half l = __float2half_rn(s - __half2float(h));
    uint32_t boff = SWZ128((uint32_t)(o * 128 + c * 2));
    g_WtapH[k * 8192 + (boff >> 1)] = *reinterpret_cast<unsigned short*>(&h);
    g_WtapL[k * 8192 + (boff >> 1)] = *reinterpret_cast<unsigned short*>(&l);
}

// ---------------------------------------------------------------------------
// L2: k_beff — bias_eff + zero stats accumulators (graph-replay safe)
// ---------------------------------------------------------------------------
__global__ void __launch_bounds__(128) k_beff(const float* __restrict__ tcn_w,
                                              const float* __restrict__ gcn_b,
                                              const float* __restrict__ tcn_b) {
    __shared__ float red[128];
    __shared__ float Bk[KT_];
    int o = blockIdx.x, o2 = threadIdx.x;
    if (o2 == 0) { g_sum[o] = 0.0; g_sum2[o] = 0.0; }
    float gb = gcn_b[o2];
    const float* wrow = tcn_w + ((size_t)o * O_ + o2) * KT_;
    #pragma unroll
    for (int k = 0; k < KT_; k++) {
        red[o2] = wrow[k] * gb;
        __syncthreads();
        for (int st = 64; st > 0; st >>= 1) {
            if (o2 < st) red[o2] += red[o2 + st];
            __syncthreads();
        }
        if (o2 == 0) Bk[k] = red[0];
        __syncthreads();
    }
    float tb = tcn_b[o];
    for (int t = threadIdx.x; t < TO_; t += 128) {
        float s = tb;
        #pragma unroll
        for (int k = 0; k < KT_; k++) {
            int tp = 2 * t + k - 4;
            if (tp >= 0 && tp < T_) s += Bk[k];
        }
        g_beff[o * TO_ + t] = s;
    }
}

// ---------------------------------------------------------------------------
// L3: k_aggp — agg in phase-split transposed fp16 layout (single array)
// ---------------------------------------------------------------------------
__global__ void __launch_bounds__(256) k_aggp(const float* __restrict__ x,
                                              const float* __restrict__ A_parts,
                                              const float* __restrict__ ei) {
    __shared__ float sx[1600];
    __shared__ float As[625];
    __shared__ __align__(16) unsigned short souts[1600];
    int row = blockIdx.x, n = blockIdx.y, tid = threadIdx.x;
    int phase = (row >= 224) ? 1 : 0;
    int e = phase ? (row - 224) : row;
    int t_in = 2 * (e - 2) + phase;
    bool valid = (t_in >= 0) && (t_in < T_);

    if (valid) {
        float e0 = ei[0], e1 = ei[1], e2 = ei[2];
        for (int i = tid; i < 625; i += 256)
            As[i] = A_parts[i] * e0 + A_parts[625 + i] * e1 + A_parts[1250 + i] * e2;
        const float* xb = x + ((size_t)n * C_) * TV_ + t_in * V_;
        for (int i = tid; i < 1600; i += 256) {
            int c = i / 25, w = i - c * 25;
            sx[i] = xb[c * TV_ + w];
        }
        __syncthreads();
        for (int i = tid; i < 1600; i += 256) {
            int v = i >> 6, c = i & 63;
            float s = 0.f;
            #pragma unroll
            for (int w = 0; w < 25; w++) s += sx[c * 25 + w] * As[w * 25 + v];
            __half h = __float2half_rn(s);
            souts[v * 64 + c] = *reinterpret_cast<unsigned short*>(&h);
        }
        __syncthreads();
        int r7 = row & 7;
        for (int j = tid; j < 200; j += 256) {
            int v = j >> 3, q = j & 7;
            uint4 val = *(const uint4*)&souts[v * 64 + ((q ^ r7) << 3)];
            *((uint4*)(g_aggB + (((size_t)(n * 25 + v) * ROWS_ + row) << 6)) + q) = val;
        }
    } else {
        for (int j = tid; j < 200; j += 256) {
            int v = j >> 3, q = j & 7;
            *((uint4*)(g_aggB + (((size_t)(n * 25 + v) * ROWS_ + row) << 6)) + q) =
                make_uint4(0, 0, 0, 0);
        }
    }
}

// ---------------------------------------------------------------------------
// L4 (profiled slot): k_tcn_mma — tap-shift HMMA fp16, A-split 2-term,
// double-buffered A via cp.async, fused BN-stats epilogue.
// smem: B [4 sec x 72 rows x 128B] = 36KB | A buf0 32KB | A buf1 32KB
// ---------------------------------------------------------------------------
#define R_SEC  72
#define SEC_B  (R_SEC * 128)          // 9216
#define TB_OFF 0
#define TA0    36864
#define TA1    69632
#define A_LOSZ 16384
#define SMEM_TOT 102400

__global__ void __launch_bounds__(256, 2) k_tcn_mma() {
    extern __shared__ __align__(16) unsigned char smem[];
    int tid = threadIdx.x, lane = tid & 31, wid = tid >> 5;
    int wm = wid >> 2, wn = wid & 3;
    int t0 = blockIdx.x * 64;
    int v0 = blockIdx.y * 2;
    int n = blockIdx.z;
    uint32_t sbase = smem_u32(smem);

    // ---- B copy (single fp16 array): 4 sections (vsec,phase) x 72 rows
    for (int j = tid; j < 2304; j += 256) {
        int sec = j / 576;
        int rq = j - sec * 576;
        int row = rq >> 3, q = rq & 7;
        int vsec = sec >> 1, phase = sec & 1;
        int vv = v0 + vsec;
        uint4 val = make_uint4(0, 0, 0, 0);
        if (row < 68 && vv < V_) {
            int grow = (phase ? 224 : 0) + t0 + row;
            val = *((const uint4*)(g_aggB +
                    (((size_t)(n * V_ + vv) * ROWS_ + grow) << 6)) + q);
        }
        *((uint4*)(smem + TB_OFF + sec * SEC_B + row * 128) + q) = val;
    }

    // ---- prologue: A tap 0 -> buf0 via cp.async
    {
        #pragma unroll
        for (int i = 0; i < 8; i++) {
            int j = tid + 256 * i;            // 0..2047
            int p = j >> 10, idx = j & 1023;
            cp_async16(sbase + TA0 + p * A_LOSZ + idx * 16,
                       (const void*)((p ? g_WtapL : g_WtapH) + idx * 8));
        }
        CP_COMMIT();
    }

    // fragment addressing
    int la_row = ((lane >> 3) & 1) * 8 + (lane & 7);
    uint32_t xorA = (uint32_t)((lane & 7) << 4);
    uint32_t la_col = ((lane >> 4) & 1) * 16;
    uint32_t aRow = (uint32_t)(wm * 64 + la_row) * 128;
    int vsec_w = wn >> 1, trow = (wn & 1) * 32;
    uint32_t lb_col = (uint32_t)(((lane >> 3) & 1) * 16);
    uint32_t lrow8 = (uint32_t)(((lane >> 4) & 1) * 8 + (lane & 7));

    float acc[4][4][4] = {};

    CP_WAIT0();
    __syncthreads();   // B + A(tap0) visible

    for (int k = 0; k < 9; k++) {
        uint32_t abuf = (k & 1) ? TA1 : TA0;
        // issue next tap copy into the other buffer
        if (k < 8) {
            uint32_t nbuf = (k & 1) ? TA0 : TA1;
            const unsigned short* srcH = g_WtapH + (k + 1) * 8192;
            const unsigned short* srcL = g_WtapL + (k + 1) * 8192;
            #pragma unroll
            for (int i = 0; i < 8; i++) {
                int j = tid + 256 * i;
                int p = j >> 10, idx = j & 1023;
                cp_async16(sbase + nbuf + p * A_LOSZ + idx * 16,
                           (const void*)((p ? srcL : srcH) + idx * 8));
            }
            CP_COMMIT();
        }

        int phase = k & 1, jt = k >> 1;
        uint32_t secoff = (uint32_t)(vsec_w * 2 + phase) * SEC_B;
        uint32_t xorB = (uint32_t)(((jt + (lane & 7)) & 7) << 4);
        uint32_t rb4 = (uint32_t)(jt + trow) + lrow8;

        #pragma unroll
        for (int ks = 0; ks < 4; ks++) {
            uint32_t cb = ((uint32_t)(ks * 32) + lb_col) ^ xorB;
            uint32_t bh[4][2];
            {
                uint32_t a0 = sbase + TB_OFF + secoff + rb4 * 128 + cb;
                ldsm_x4(&bh[0][0], a0);
                ldsm_x4(&bh[2][0], a0 + 16 * 128);
            }
            uint32_t ca = ((uint32_t)(ks * 32) + la_col) ^ xorA;
            #pragma unroll
            for (int mt = 0; mt < 4; mt++) {
                uint32_t ah[4], al[4];
                ldsm_x4(ah, sbase + abuf + aRow + mt * 2048 + ca);
                ldsm_x4(al, sbase + abuf + A_LOSZ + aRow + mt * 2048 + ca);
                #pragma unroll
                for (int nt = 0; nt < 4; nt++) {
                    mma_f16(acc[mt][nt], ah, bh[nt]);
                    mma_f16(acc[mt][nt], al, bh[nt]);
                }
            }
        }

        if (k < 8) CP_WAIT0();
        __syncthreads();   // new A buffer visible to all; ldsm of cur done
    }

    // ---- epilogue + fused stats (smem reuse after final sync)
    float* ssum = (float*)smem;
    float* ssum2 = ssum + 128;
    if (tid < 128) { ssum[tid] = 0.f; ssum2[tid] = 0.f; }
    __syncthreads();

    float* Out = g_xtcn + (size_t)n * O_ * TOV_;
    int qr = lane >> 2, qc = (lane & 3) * 2;
    int vv = v0 + vsec_w;
    #pragma unroll
    for (int mt = 0; mt < 4; mt++) {
        #pragma unroll
        for (int hh = 0; hh < 2; hh++) {
            int o = wm * 64 + mt * 16 + qr + hh * 8;
            const float* be = g_beff + o * TO_;
            float* orow = Out + (size_t)o * TOV_;
            float s1 = 0.f, s2 = 0.f;
            #pragma unroll
            for (int nt = 0; nt < 4; nt++) {
                int t = t0 + trow + nt * 8 + qc;
                if (vv < V_) {
                    if (t < TO_) {
                        float y = acc[mt][nt][hh * 2 + 0] + be[t];
                        orow[t * V_ + vv] = y;
                        s1 += y; s2 += y * y;
                    }
                    if (t + 1 < TO_) {
                        float y = acc[mt][nt][hh * 2 + 1] + be[t + 1];
                        orow[(t + 1) * V_ + vv] = y;
                        s1 += y; s2 += y * y;
                    }
                }
            }
            s1 += __shfl_xor_sync(0xFFFFFFFFu, s1, 1);
            s1 += __shfl_xor_sync(0xFFFFFFFFu, s1, 2);
            s2 += __shfl_xor_sync(0xFFFFFFFFu, s2, 1);
            s2 += __shfl_xor_sync(0xFFFFFFFFu, s2, 2);
            if ((lane & 3) == 0) {
                atomicAdd(&ssum[o], s1);
                atomicAdd(&ssum2[o], s2);
            }
        }
    }
    __syncthreads();
    if (tid < 128) {
        atomicAdd(&g_sum[tid], (double)ssum[tid]);
        atomicAdd(&g_sum2[tid], (double)ssum2[tid]);
    }
}

// ---------------------------------------------------------------------------
// L5: k_statsfin — finalize BN scale/shift
// ---------------------------------------------------------------------------
__global__ void k_statsfin(const float* __restrict__ gamma,
                           const float* __restrict__ beta) {
    int o = threadIdx.x;
    double cnt = (double)N_ * (double)TOV_;
    double mean = g_sum[o] / cnt;
    double var = g_sum2[o] / cnt - mean * mean;
    float rstd = (float)(1.0 / sqrt(var + 1e-5));
    float sc = gamma[o] * rstd;
    g_scale[o] = sc;
    g_shift[o] = beta[o] - (float)mean * sc;
}

// ---------------------------------------------------------------------------
// L6: k_final — residual GEMM fused with BN affine + add + ReLU (R10 version)
// ---------------------------------------------------------------------------
__global__ void __launch_bounds__(256) k_final(const float* __restrict__ x,
                                               const float* __restrict__ W,
                                               const float* __restrict__ bias,
                                               float* __restrict__ out) {
    __shared__ float Wt[C_][132];
    __shared__ float Is[16][128];
    __shared__ int st2[128];
    __shared__ int sv[128];
    int tid = threadIdx.x;
    int n = blockIdx.y;
    int s0 = blockIdx.x * 128;
    const float* In = x + (size_t)n * C_ * TV_;

    #pragma unroll
    for (int i = 0; i < 32; i++) {
        int e = i * 256 + tid;
        int c = e & 63, o = e >> 6;
        Wt[c][o] = W[o * C_ + c];
    }
    if (tid < 128) {
        int s = s0 + tid;
        if (s < TOV_) { st2[tid] = (s / V_) * 2; sv[tid] = s % V_; }
        else          { st2[tid] = 0;            sv[tid] = 0; }
    }
    __syncthreads();

    int myS = tid & 127;
    int my_t2 = st2[myS];
    int my_v  = sv[myS];
    int kk_par = tid >> 7;
    int tx = tid & 15, ty = tid >> 4;
    float acc[8][8] = {};

    for (int kt = 0; kt < 4; kt++) {
        __syncthreads();
        #pragma unroll
        for (int i = 0; i < 8; i++) {
            int cl = 2 * i + kk_par;
            int c = kt * 16 + cl;
            Is[cl][myS] = In[(c * T_ + my_t2) * V_ + my_v];
        }
        __syncthreads();
        #pragma unroll
        for (int c = 0; c < 16; c++) {
            float4 a0 = *(const float4*)&Wt[kt * 16 + c][ty * 4];
            float4 a1 = *(const float4*)&Wt[kt * 16 + c][64 + ty * 4];
            float4 b0 = *(const float4*)&Is[c][tx * 4];
            float4 b1 = *(const float4*)&Is[c][64 + tx * 4];
            float a[8] = {a0.x, a0.y, a0.z, a0.w, a1.x, a1.y, a1.z, a1.w};
            float b[8] = {b0.x, b0.y, b0.z, b0.w, b1.x, b1.y, b1.z, b1.w};
            #pragma unroll
            for (int i = 0; i < 8; i++)
                #pragma unroll
                for (int j = 0; j < 8; j++)
                    acc[i][j] += a[i] * b[j];
        }
    }

    const float* Tcn = g_xtcn + (size_t)n * O_ * TOV_;
    #pragma unroll
    for (int i = 0; i < 8; i++) {
        int o = (i < 4) ? (ty * 4 + i) : (64 + ty * 4 + i - 4);
        float bo = __ldg(&bias[o]);
        float sc = g_scale[o];
        float sh = g_shift[o];
        #pragma unroll
        for (int j = 0; j < 8; j++) {
            int s = s0 + ((j < 4) ? (tx * 4 + j) : (64 + tx * 4 + j - 4));
            if (s < TOV_) {
                float bn = Tcn[o * TOV_ + s] * sc + sh;
                float v = bn + acc[i][j] + bo;
                out[((size_t)n * O_ + o) * TOV_ + s] = fmaxf(v, 0.f);
            }
        }
    }
}

// ---------------------------------------------------------------------------
extern "C" void kernel_launch(void* const* d_in, const int* in_sizes, int n_in,
                              void* d_out, int out_size) {
    const float* x       = (const float*)d_in[0];
    const float* A_parts = (const float*)d_in[1];
    const float* ei      = (const float*)d_in[2];
    const float* gcn_w   = (const float*)d_in[3];
    const float* gcn_b   = (const float*)d_in[4];
    const float* tcn_w   = (const float*)d_in[5];
    const float* tcn_b   = (const float*)d_in[6];
    const float* bn_g    = (const float*)d_in[7];
    const float* bn_b    = (const float*)d_in[8];
    const float* res_w   = (const float*)d_in[9];
    const float* res_b   = (const float*)d_in[10];
    float* out = (float*)d_out;

    cudaFuncSetAttribute(k_tcn_mma, cudaFuncAttributeMaxDynamicSharedMemorySize,
                         SMEM_TOT);

    k_wprep<<<576, 128>>>(tcn_w, gcn_w);                 // 1
    k_beff<<<O_, 128>>>(tcn_w, gcn_b, tcn_b);            // 2
    dim3 gagg(ROWS_, N_);
    k_aggp<<<gagg, 256>>>(x, A_parts, ei);               // 3
    dim3 gtcn(3, 13, N_);
    k_tcn_mma<<<gtcn, 256, SMEM_TOT>>>();                // 4  <- profiled
    k_statsfin<<<1, 128>>>(bn_g, bn_b);                  // 5
    dim3 gfin((TOV_ + 127) / 128, N_);
    k_final<<<gfin, 256>>>(x, res_w, res_b, out);        // 6
}

// round 14
// speedup vs baseline: 1.7506x; 1.2059x over previous
#include <cuda_runtime.h>
#include <cuda_fp16.h>
#include <cstdint>

// Problem constants
#define N_   32
#define C_   64
#define T_   300
#define V_   25
#define O_   128
#define TO_  150
#define TV_  7500
#define TOV_ 3750
#define KT_  9

// Phase-split transposed agg layout: [n][v][row][c], row<224: even phase
// (t_in = 2*(row-2)), row>=224: odd phase (t_in = 2*(row-224-2)+1).
#define ROWS_ 448

__device__ float g_xtcn[N_ * O_ * TO_ * V_];         // 61.4 MB fp32
__device__ float g_beff[O_ * TO_];
__device__ __align__(16) unsigned short g_aggB[(size_t)N_ * V_ * ROWS_ * 64];  // fp16
__device__ __align__(16) unsigned short g_WtapH[9 * 128 * 64];  // fp16 (single term)
__device__ __align__(16) unsigned short g_WresH[128 * 64];      // res_w hi
__device__ __align__(16) unsigned short g_WresL[128 * 64];      // res_w lo
__device__ double g_sum[O_];
__device__ double g_sum2[O_];
__device__ float g_scale[O_];
__device__ float g_shift[O_];

// ---------------- PTX helpers ------------------------------------------------
__device__ __forceinline__ uint32_t smem_u32(const void* p) {
    uint32_t a;
    asm("{ .reg .u64 t; cvta.to.shared.u64 t, %1; cvt.u32.u64 %0, t; }" : "=r"(a) : "l"(p));
    return a;
}
__device__ __forceinline__ void ldsm_x4(uint32_t* r, uint32_t addr) {
    asm volatile("ldmatrix.sync.aligned.m8n8.x4.shared.b16 {%0,%1,%2,%3}, [%4];"
                 : "=r"(r[0]), "=r"(r[1]), "=r"(r[2]), "=r"(r[3]) : "r"(addr));
}
__device__ __forceinline__ void mma_f16(float* d, const uint32_t* a, const uint32_t* b) {
    asm volatile(
        "mma.sync.aligned.m16n8k16.row.col.f32.f16.f16.f32 "
        "{%0,%1,%2,%3}, {%4,%5,%6,%7}, {%8,%9}, {%0,%1,%2,%3};"
        : "+f"(d[0]), "+f"(d[1]), "+f"(d[2]), "+f"(d[3])
        : "r"(a[0]), "r"(a[1]), "r"(a[2]), "r"(a[3]), "r"(b[0]), "r"(b[1]));
}
__device__ __forceinline__ void cp_async16(uint32_t dst, const void* src) {
    asm volatile("cp.async.cg.shared.global [%0], [%1], 16;" :: "r"(dst), "l"(src));
}
#define CP_COMMIT() asm volatile("cp.async.commit_group;" ::: "memory")
#define CP_WAIT0()  asm volatile("cp.async.wait_group 0;" ::: "memory")
#define SWZ128(x) ((x) ^ (((x) >> 3) & 0x70))

// ---------------------------------------------------------------------------
// L1: k_wprep — fused gcn*tcn weight -> swizzled fp16 per-tap images.
// ---------------------------------------------------------------------------
__global__ void __launch_bounds__(128) k_wprep(const float* __restrict__ tcn_w,
                                               const float* __restrict__ gcn_w) {
    __shared__ float gc[O_];
    int ck = blockIdx.x;
    int c = ck / KT_, k = ck % KT_;
    int o = threadIdx.x;
    gc[o] = gcn_w[o * C_ + c];
    __syncthreads();
    const float* wrow = tcn_w + (size_t)o * O_ * KT_ + k;
    float s = 0.f;
    #pragma unroll 8
    for (int o2 = 0; o2 < O_; o2++) s += wrow[o2 * KT_] * gc[o2];
    __half h = __float2half_rn(s);
    uint32_t boff = SWZ128((uint32_t)(o * 128 + c * 2));
    g_WtapH[k * 8192 + (boff >> 1)] = *reinterpret_cast<unsigned short*>(&h);
}

// ---------------------------------------------------------------------------
// L2: k_beff — bias_eff + zero stats accumulators + res_w hi/lo images
// ---------------------------------------------------------------------------
__global__ void __launch_bounds__(128) k_beff(const float* __restrict__ tcn_w,
                                              const float* __restrict__ gcn_b,
                                              const float* __restrict__ tcn_b,
                                              const float* __restrict__ res_w) {
    __shared__ float red[128];
    __shared__ float Bk[KT_];
    int o = blockIdx.x, o2 = threadIdx.x;
    if (o2 == 0) { g_sum[o] = 0.0; g_sum2[o] = 0.0; }
    if (o2 < 64) {
        float w = res_w[o * C_ + o2];
        __half h = __float2half_rn(w);
        __half l = __float2half_rn(w - __half2float(h));
        uint32_t boff = SWZ128((uint32_t)(o * 128 + o2 * 2));
        g_WresH[boff >> 1] = *reinterpret_cast<unsigned short*>(&h);
        g_WresL[boff >> 1] = *reinterpret_cast<unsigned short*>(&l);
    }
    float gb = gcn_b[o2];
    const float* wrow = tcn_w + ((size_t)o * O_ + o2) * KT_;
    #pragma unroll
    for (int k = 0; k < KT_; k++) {
        red[o2] = wrow[k] * gb;
        __syncthreads();
        for (int st = 64; st > 0; st >>= 1) {
            if (o2 < st) red[o2] += red[o2 + st];
            __syncthreads();
        }
        if (o2 == 0) Bk[k] = red[0];
        __syncthreads();
    }
    float tb = tcn_b[o];
    for (int t = threadIdx.x; t < TO_; t += 128) {
        float s = tb;
        #pragma unroll
        for (int k = 0; k < KT_; k++) {
            int tp = 2 * t + k - 4;
            if (tp >= 0 && tp < T_) s += Bk[k];
        }
        g_beff[o * TO_ + t] = s;
    }
}

// ---------------------------------------------------------------------------
// L3: k_aggp — agg in phase-split transposed fp16 layout
// ---------------------------------------------------------------------------
__global__ void __launch_bounds__(256) k_aggp(const float* __restrict__ x,
                                              const float* __restrict__ A_parts,
                                              const float* __restrict__ ei) {
    __shared__ float sx[1600];
    __shared__ float As[625];
    __shared__ __align__(16) unsigned short souts[1600];
    int row = blockIdx.x, n = blockIdx.y, tid = threadIdx.x;
    int phase = (row >= 224) ? 1 : 0;
    int e = phase ? (row - 224) : row;
    int t_in = 2 * (e - 2) + phase;
    bool valid = (t_in >= 0) && (t_in < T_);

    if (valid) {
        float e0 = ei[0], e1 = ei[1], e2 = ei[2];
        for (int i = tid; i < 625; i += 256)
            As[i] = A_parts[i] * e0 + A_parts[625 + i] * e1 + A_parts[1250 + i] * e2;
        const float* xb = x + ((size_t)n * C_) * TV_ + t_in * V_;
        for (int i = tid; i < 1600; i += 256) {
            int c = i / 25, w = i - c * 25;
            sx[i] = xb[c * TV_ + w];
        }
        __syncthreads();
        for (int i = tid; i < 1600; i += 256) {
            int v = i >> 6, c = i & 63;
            float s = 0.f;
            #pragma unroll
            for (int w = 0; w < 25; w++) s += sx[c * 25 + w] * As[w * 25 + v];
            __half h = __float2half_rn(s);
            souts[v * 64 + c] = *reinterpret_cast<unsigned short*>(&h);
        }
        __syncthreads();
        int r7 = row & 7;
        for (int j = tid; j < 200; j += 256) {
            int v = j >> 3, q = j & 7;
            uint4 val = *(const uint4*)&souts[v * 64 + ((q ^ r7) << 3)];
            *((uint4*)(g_aggB + (((size_t)(n * 25 + v) * ROWS_ + row) << 6)) + q) = val;
        }
    } else {
        for (int j = tid; j < 200; j += 256) {
            int v = j >> 3, q = j & 7;
            *((uint4*)(g_aggB + (((size_t)(n * 25 + v) * ROWS_ + row) << 6)) + q) =
                make_uint4(0, 0, 0, 0);
        }
    }
}

// ---------------------------------------------------------------------------
// L4 (profiled slot): k_tcn_mma — tap-shift HMMA fp16 single-term,
// double-buffered A via cp.async, fused BN-stats epilogue.
// smem: B [4 sec x 72 rows x 128B] = 36KB | A buf0 16KB | A buf1 16KB
// ---------------------------------------------------------------------------
#define R_SEC  72
#define SEC_B  (R_SEC * 128)          // 9216
#define TB_OFF 0
#define TA0    36864
#define TA1    53248
#define SMEM_TOT 69632

__global__ void __launch_bounds__(256, 2) k_tcn_mma() {
    extern __shared__ __align__(16) unsigned char smem[];
    int tid = threadIdx.x, lane = tid & 31, wid = tid >> 5;
    int wm = wid >> 2, wn = wid & 3;
    int t0 = blockIdx.x * 64;
    int v0 = blockIdx.y * 2;
    int n = blockIdx.z;
    uint32_t sbase = smem_u32(smem);

    // ---- B copy: 4 sections (vsec,phase) x 72 rows
    for (int j = tid; j < 2304; j += 256) {
        int sec = j / 576;
        int rq = j - sec * 576;
        int row = rq >> 3, q = rq & 7;
        int vsec = sec >> 1, phase = sec & 1;
        int vv = v0 + vsec;
        uint4 val = make_uint4(0, 0, 0, 0);
        if (row < 68 && vv < V_) {
            int grow = (phase ? 224 : 0) + t0 + row;
            val = *((const uint4*)(g_aggB +
                    (((size_t)(n * V_ + vv) * ROWS_ + grow) << 6)) + q);
        }
        *((uint4*)(smem + TB_OFF + sec * SEC_B + row * 128) + q) = val;
    }

    // ---- prologue: A tap 0 -> buf0 via cp.async (16KB = 1024 x 16B)
    {
        #pragma unroll
        for (int i = 0; i < 4; i++) {
            int idx = tid + 256 * i;          // 0..1023
            cp_async16(sbase + TA0 + idx * 16, (const void*)(g_WtapH + idx * 8));
        }
        CP_COMMIT();
    }

    // fragment addressing
    int la_row = ((lane >> 3) & 1) * 8 + (lane & 7);
    uint32_t xorA = (uint32_t)((lane & 7) << 4);
    uint32_t la_col = ((lane >> 4) & 1) * 16;
    uint32_t aRow = (uint32_t)(wm * 64 + la_row) * 128;
    int vsec_w = wn >> 1, trow = (wn & 1) * 32;
    uint32_t lb_col = (uint32_t)(((lane >> 3) & 1) * 16);
    uint32_t lrow8 = (uint32_t)(((lane >> 4) & 1) * 8 + (lane & 7));

    float acc[4][4][4] = {};

    CP_WAIT0();
    __syncthreads();

    for (int k = 0; k < 9; k++) {
        uint32_t abuf = (k & 1) ? TA1 : TA0;
        if (k < 8) {
            uint32_t nbuf = (k & 1) ? TA0 : TA1;
            const unsigned short* srcH = g_WtapH + (k + 1) * 8192;
            #pragma unroll
            for (int i = 0; i < 4; i++) {
                int idx = tid + 256 * i;
                cp_async16(sbase + nbuf + idx * 16, (const void*)(srcH + idx * 8));
            }
            CP_COMMIT();
        }

        int phase = k & 1, jt = k >> 1;
        uint32_t secoff = (uint32_t)(vsec_w * 2 + phase) * SEC_B;
        uint32_t xorB = (uint32_t)(((jt + (lane & 7)) & 7) << 4);
        uint32_t rb4 = (uint32_t)(jt + trow) + lrow8;

        #pragma unroll
        for (int ks = 0; ks < 4; ks++) {
            uint32_t cb = ((uint32_t)(ks * 32) + lb_col) ^ xorB;
            uint32_t bh[4][2];
            {
                uint32_t a0 = sbase + TB_OFF + secoff + rb4 * 128 + cb;
                ldsm_x4(&bh[0][0], a0);
                ldsm_x4(&bh[2][0], a0 + 16 * 128);
            }
            uint32_t ca = ((uint32_t)(ks * 32) + la_col) ^ xorA;
            #pragma unroll
            for (int mt = 0; mt < 4; mt++) {
                uint32_t ah[4];
                ldsm_x4(ah, sbase + abuf + aRow + mt * 2048 + ca);
                #pragma unroll
                for (int nt = 0; nt < 4; nt++)
                    mma_f16(acc[mt][nt], ah, bh[nt]);
            }
        }

        if (k < 8) CP_WAIT0();
        __syncthreads();
    }

    // ---- epilogue + fused stats
    float* ssum = (float*)smem;
    float* ssum2 = ssum + 128;
    if (tid < 128) { ssum[tid] = 0.f; ssum2[tid] = 0.f; }
    __syncthreads();

    float* Out = g_xtcn + (size_t)n * O_ * TOV_;
    int qr = lane >> 2, qc = (lane & 3) * 2;
    int vv = v0 + vsec_w;
    #pragma unroll
    for (int mt = 0; mt < 4; mt++) {
        #pragma unroll
        for (int hh = 0; hh < 2; hh++) {
            int o = wm * 64 + mt * 16 + qr + hh * 8;
            const float* be = g_beff + o * TO_;
            float* orow = Out + (size_t)o * TOV_;
            float s1 = 0.f, s2 = 0.f;
            #pragma unroll
            for (int nt = 0; nt < 4; nt++) {
                int t = t0 + trow + nt * 8 + qc;
                if (vv < V_) {
                    if (t < TO_) {
                        float y = acc[mt][nt][hh * 2 + 0] + be[t];
                        orow[t * V_ + vv] = y;
                        s1 += y; s2 += y * y;
                    }
                    if (t + 1 < TO_) {
                        float y = acc[mt][nt][hh * 2 + 1] + be[t + 1];
                        orow[(t + 1) * V_ + vv] = y;
                        s1 += y; s2 += y * y;
                    }
                }
            }
            s1 += __shfl_xor_sync(0xFFFFFFFFu, s1, 1);
            s1 += __shfl_xor_sync(0xFFFFFFFFu, s1, 2);
            s2 += __shfl_xor_sync(0xFFFFFFFFu, s2, 1);
            s2 += __shfl_xor_sync(0xFFFFFFFFu, s2, 2);
            if ((lane & 3) == 0) {
                atomicAdd(&ssum[o], s1);
                atomicAdd(&ssum2[o], s2);
            }
        }
    }
    __syncthreads();
    if (tid < 128) {
        atomicAdd(&g_sum[tid], (double)ssum[tid]);
        atomicAdd(&g_sum2[tid], (double)ssum2[tid]);
    }
}

// ---------------------------------------------------------------------------
// L5: k_statsfin — finalize BN scale/shift (res_b folded into shift)
// ---------------------------------------------------------------------------
__global__ void k_statsfin(const float* __restrict__ gamma,
                           const float* __restrict__ beta,
                           const float* __restrict__ res_b) {
    int o = threadIdx.x;
    double cnt = (double)N_ * (double)TOV_;
    double mean = g_sum[o] / cnt;
    double var = g_sum2[o] / cnt - mean * mean;
    float rstd = (float)(1.0 / sqrt(var + 1e-5));
    float sc = gamma[o] * rstd;
    g_scale[o] = sc;
    g_shift[o] = beta[o] - (float)mean * sc + res_b[o];
}

// ---------------------------------------------------------------------------
// L6: k_fin_mma — residual HMMA (K=64, res_w 2-term) + BN + add + ReLU.
// CTA = (contiguous s-block of 128, n). Output layout identical to R10 k_final
// (o rows, contiguous s) — coalesced epilogue.
// smem: B [128 s][64 c] fp16 swizzled 16KB | A hi 16KB | A lo 16KB
// ---------------------------------------------------------------------------
#define FB_OFF 0
#define FAH    16384
#define FAL    32768
#define SMEM_FIN 49152

__global__ void __launch_bounds__(256, 2) k_fin_mma(const float* __restrict__ x,
                                                    float* __restrict__ out) {
    extern __shared__ __align__(16) unsigned char smem[];
    int tid = threadIdx.x, lane = tid & 31, wid = tid >> 5;
    int wm = wid >> 2, wn = wid & 3;
    int n = blockIdx.y;
    int s0 = blockIdx.x * 128;
    uint32_t sbase = smem_u32(smem);

    // A copy (res_w hi/lo images, 16KB each = 1024 uint4 each)
    #pragma unroll
    for (int i = 0; i < 8; i++) {
        int j = tid + 256 * i;                // 0..2047
        int p = j >> 10, idx = j & 1023;
        *((uint4*)(smem + (p ? FAL : FAH)) + idx) =
            *((const uint4*)(p ? g_WresL : g_WresH) + idx);
    }

    // B gather: thread covers s-row r, 32 c values (half selects c range)
    {
        int r = tid & 127, half = tid >> 7;
        int s = s0 + r;
        bool valid = s < TOV_;
        int t2 = valid ? (s / V_) * 2 : 0;
        int v = valid ? (s % V_) : 0;
        const float* xb = x + (size_t)n * C_ * TV_ + (size_t)t2 * V_ + v;
        int xors = (r & 7) << 4;
        #pragma unroll
        for (int j = 0; j < 16; j++) {
            int c0 = half * 32 + j * 2;
            float f0 = valid ? xb[(size_t)c0 * TV_] : 0.f;
            float f1 = valid ? xb[(size_t)(c0 + 1) * TV_] : 0.f;
            __half h0 = __float2half_rn(f0);
            __half h1 = __float2half_rn(f1);
            uint32_t pair = (uint32_t)*reinterpret_cast<unsigned short*>(&h0) |
                            ((uint32_t)*reinterpret_cast<unsigned short*>(&h1) << 16);
            uint32_t off = (uint32_t)(r * 128 + ((c0 * 2) ^ xors));
            *reinterpret_cast<uint32_t*>(smem + FB_OFF + off) = pair;
        }
    }
    __syncthreads();

    // fragment addressing
    int la_row = ((lane >> 3) & 1) * 8 + (lane & 7);
    uint32_t xorA = (uint32_t)((lane & 7) << 4);
    uint32_t la_col = ((lane >> 4) & 1) * 16;
    uint32_t aRow = (uint32_t)(wm * 64 + la_row) * 128;
    uint32_t lb_col = (uint32_t)(((lane >> 3) & 1) * 16);
    uint32_t lrow8 = (uint32_t)(((lane >> 4) & 1) * 8 + (lane & 7));
    uint32_t rb4 = (uint32_t)(wn * 32) + lrow8;
    uint32_t xorB = (uint32_t)((lane & 7) << 4);

    float acc[4][4][4] = {};

    #pragma unroll
    for (int ks = 0; ks < 4; ks++) {
        uint32_t cb = ((uint32_t)(ks * 32) + lb_col) ^ xorB;
        uint32_t bh[4][2];
        {
            uint32_t a0 = sbase + FB_OFF + rb4 * 128 + cb;
            ldsm_x4(&bh[0][0], a0);
            ldsm_x4(&bh[2][0], a0 + 16 * 128);
        }
        uint32_t ca = ((uint32_t)(ks * 32) + la_col) ^ xorA;
        #pragma unroll
        for (int mt = 0; mt < 4; mt++) {
            uint32_t ah[4], al[4];
            ldsm_x4(ah, sbase + FAH + aRow + mt * 2048 + ca);
            ldsm_x4(al, sbase + FAL + aRow + mt * 2048 + ca);
            #pragma unroll
            for (int nt = 0; nt < 4; nt++) {
                mma_f16(acc[mt][nt], ah, bh[nt]);
                mma_f16(acc[mt][nt], al, bh[nt]);
            }
        }
    }

    // epilogue: out = relu(xtcn*scale + shift + res)   (res_b in shift)
    const float* Tcn = g_xtcn + (size_t)n * O_ * TOV_;
    float* Out = out + (size_t)n * O_ * TOV_;
    int qr = lane >> 2, qc = (lane & 3) * 2;
    #pragma unroll
    for (int mt = 0; mt < 4; mt++) {
        #pragma unroll
        for (int hh = 0; hh < 2; hh++) {
            int o = wm * 64 + mt * 16 + qr + hh * 8;
            float sc = g_scale[o];
            float sh = g_shift[o];
            const float* trow = Tcn + (size_t)o * TOV_;
            float* orow = Out + (size_t)o * TOV_;
            #pragma unroll
            for (int nt = 0; nt < 4; nt++) {
                int s = s0 + wn * 32 + nt * 8 + qc;
                if (s < TOV_) {
                    float y = trow[s] * sc + sh + acc[mt][nt][hh * 2 + 0];
                    orow[s] = fmaxf(y, 0.f);
                }
                if (s + 1 < TOV_) {
                    float y = trow[s + 1] * sc + sh + acc[mt][nt][hh * 2 + 1];
                    orow[s + 1] = fmaxf(y, 0.f);
                }
            }
        }
    }
}

// ---------------------------------------------------------------------------
extern "C" void kernel_launch(void* const* d_in, const int* in_sizes, int n_in,
                              void* d_out, int out_size) {
    const float* x       = (const float*)d_in[0];
    const float* A_parts = (const float*)d_in[1];
    const float* ei      = (const float*)d_in[2];
    const float* gcn_w   = (const float*)d_in[3];
    const float* gcn_b   = (const float*)d_in[4];
    const float* tcn_w   = (const float*)d_in[5];
    const float* tcn_b   = (const float*)d_in[6];
    const float* bn_g    = (const float*)d_in[7];
    const float* bn_b    = (const float*)d_in[8];
    const float* res_w   = (const float*)d_in[9];
    const float* res_b   = (const float*)d_in[10];
    float* out = (float*)d_out;

    cudaFuncSetAttribute(k_tcn_mma, cudaFuncAttributeMaxDynamicSharedMemorySize,
                         SMEM_TOT);
    cudaFuncSetAttribute(k_fin_mma, cudaFuncAttributeMaxDynamicSharedMemorySize,
                         SMEM_FIN);

    k_wprep<<<576, 128>>>(tcn_w, gcn_w);                 // 1
    k_beff<<<O_, 128>>>(tcn_w, gcn_b, tcn_b, res_w);     // 2
    dim3 gagg(ROWS_, N_);
    k_aggp<<<gagg, 256>>>(x, A_parts, ei);               // 3
    dim3 gtcn(3, 13, N_);
    k_tcn_mma<<<gtcn, 256, SMEM_TOT>>>();                // 4  <- profiled
    k_statsfin<<<1, 128>>>(bn_g, bn_b, res_b);           // 5
    dim3 gfin((TOV_ + 127) / 128, N_);
    k_fin_mma<<<gfin, 256, SMEM_FIN>>>(x, out);          // 6
}